// round 3
// baseline (speedup 1.0000x reference)
#include <cuda_runtime.h>
#include <cuda_bf16.h>
#include <cstdint>

#define S_TOT 32768
#define CH    16
#define NCHUNK (S_TOT / CH)
#define CSIZE 4          // cluster CTAs per pipeline stage
#define EL    32         // h elements owned per CTA

// ---------------- static device scratch ----------------
__device__ float    g_fc1 [65536u * 128u];
__device__ float    g_xg0 [2u * 32768u * 512u];
__device__ float    g_xg1 [2u * 32768u * 512u];
__device__ float    g_h0  [2u * 32768u * 128u];
__device__ float    g_y   [2u * 256u * 128u];
__device__ unsigned g_wpack[3u * 512u * 64u];     // packed bf16x2: Whh0, Wih1, Whh1
__device__ float    g_b1  [512];
__device__ int      g_prog[16];                   // [seq*8 + set*4 + rank]

// ---------------- helpers ----------------
__device__ __forceinline__ int ld_acq(const int* p) {
    int v;
    asm volatile("ld.acquire.gpu.b32 %0, [%1];" : "=r"(v) : "l"(p) : "memory");
    return v;
}
__device__ __forceinline__ void st_rel(int* p, int v) {
    asm volatile("st.release.gpu.b32 [%0], %1;" :: "l"(p), "r"(v) : "memory");
}
__device__ __forceinline__ uint32_t s2u(const void* p) {
    return (uint32_t)__cvta_generic_to_shared(p);
}
__device__ __forceinline__ uint32_t mapa_u32(uint32_t la, uint32_t r) {
    uint32_t ra;
    asm("mapa.shared::cluster.u32 %0, %1, %2;" : "=r"(ra) : "r"(la), "r"(r));
    return ra;
}
__device__ __forceinline__ void st_cluster_f32(uint32_t a, float v) {
    asm volatile("st.shared::cluster.f32 [%0], %1;" :: "r"(a), "f"(v) : "memory");
}
__device__ __forceinline__ void mbar_init(uint32_t mb, uint32_t cnt) {
    asm volatile("mbarrier.init.shared.b64 [%0], %1;" :: "r"(mb), "r"(cnt) : "memory");
}
__device__ __forceinline__ void mbar_arrive_rel_cluster(uint32_t mb) {
    asm volatile("mbarrier.arrive.release.cluster.shared::cluster.b64 _, [%0];"
                 :: "r"(mb) : "memory");
}
__device__ __forceinline__ void mbar_wait(uint32_t mb, uint32_t par) {
    asm volatile(
        "{\n\t.reg .pred P;\n\t"
        "WL%=:\n\t"
        "mbarrier.try_wait.parity.acquire.cluster.shared::cta.b64 P, [%0], %1, 0x989680;\n\t"
        "@P bra.uni WD%=;\n\t"
        "bra.uni WL%=;\n\t"
        "WD%=:\n\t}"
        :: "r"(mb), "r"(par) : "memory");
}
__device__ __forceinline__ void cluster_sync() {
    asm volatile("barrier.cluster.arrive.aligned;" ::: "memory");
    asm volatile("barrier.cluster.wait.aligned;" ::: "memory");
}

__device__ __forceinline__ unsigned bf16rn_bits(float f) {
    unsigned u = __float_as_uint(f);
    return ((u + 0x7fffu + ((u >> 16) & 1u)) >> 16) & 0xffffu;
}
__device__ __forceinline__ unsigned pack2(float we, float wo) {
    unsigned lo = bf16rn_bits(we);
    unsigned t  = __float_as_uint(wo) & 0xffff0000u;
    unsigned best = t | lo;
    float bd = fabsf(__uint_as_float(best) - wo);
    unsigned c = (t + 0x10000u) | lo;
    { float d = fabsf(__uint_as_float(c) - wo); if (d < bd) { bd = d; best = c; } }
    c = (t - 0x10000u) | lo;
    { float d = fabsf(__uint_as_float(c) - wo); if (d < bd) { bd = d; best = c; } }
    return best;
}

__device__ __forceinline__ float sigf(float x) {
    return __fdividef(1.0f, 1.0f + __expf(-x));
}
__device__ __forceinline__ float tanh_(float x) {
    return fmaf(2.0f, sigf(2.0f * x), -1.0f);
}

// full 128-MAC dot (producer): h in smem, 64 packed regs
__device__ __forceinline__ float dot128(const float* h, const unsigned* w) {
    const float4* h4 = (const float4*)h;
    float a0 = 0.f, a1 = 0.f, a2 = 0.f, a3 = 0.f;
#pragma unroll
    for (int q = 0; q < 32; q++) {
        float4 hv = h4[q];
        unsigned w01 = w[2 * q], w23 = w[2 * q + 1];
        a0 = fmaf(__uint_as_float(w01 << 16), hv.x, a0);
        a1 = fmaf(__uint_as_float(w01),       hv.y, a1);
        a2 = fmaf(__uint_as_float(w23 << 16), hv.z, a2);
        a3 = fmaf(__uint_as_float(w23),       hv.w, a3);
    }
    return (a0 + a1) + (a2 + a3);
}

// ---------------- prep ----------------
__global__ void __launch_bounds__(512) prep_kernel(const float* __restrict__ Wih,
                                                   const float* __restrict__ Whh,
                                                   const float* __restrict__ bih,
                                                   const float* __restrict__ bhh) {
    int wsel = blockIdx.x;
    int j = threadIdx.x;
    const float* row;
    if (wsel == 0)      row = Whh + (size_t)j * 128;
    else if (wsel == 1) row = Wih + 512u * 128u + (size_t)j * 128;
    else                row = Whh + 512u * 128u + (size_t)j * 128;
    unsigned* dst = g_wpack + ((size_t)wsel * 512 + j) * 64;
    for (int p = 0; p < 64; p++) dst[p] = pack2(row[2 * p], row[2 * p + 1]);
    if (wsel == 1) g_b1[j] = bih[512 + j] + bhh[512 + j];
    if (wsel == 0 && j < 16) g_prog[j] = 0;
}

// ---------------- fc1 ----------------
__global__ void __launch_bounds__(256) fc1_kernel(const float* __restrict__ inp1,
                                                  const float* __restrict__ inp2,
                                                  const float* __restrict__ Wfc,
                                                  const float* __restrict__ bfc) {
    __shared__ float Ws[128][65];
    __shared__ float As[32][64];
    int tid = threadIdx.x;
    for (int i = tid; i < 128 * 64; i += 256) Ws[i >> 6][i & 63] = Wfc[i];
    int r0 = blockIdx.x * 32;
    for (int i = tid; i < 32 * 64; i += 256) {
        int r = r0 + (i >> 6), k = i & 63;
        const float* src = (r < S_TOT) ? (inp1 + (size_t)r * 64)
                                       : (inp2 + (size_t)(r - S_TOT) * 64);
        As[i >> 6][k] = src[k];
    }
    __syncthreads();
    int n = tid & 127, rb = (tid >> 7) * 16;
    float b = bfc[n];
    for (int rr = 0; rr < 16; rr++) {
        float acc = b;
#pragma unroll
        for (int k = 0; k < 64; k++) acc = fmaf(As[rb + rr][k], Ws[n][k], acc);
        g_fc1[(size_t)(r0 + rb + rr) * 128 + n] = fmaxf(acc, 0.f);
    }
}

// ---------------- xg0 GEMM ----------------
__global__ void __launch_bounds__(256) xg0_kernel(const float* __restrict__ Wih,
                                                  const float* __restrict__ bih,
                                                  const float* __restrict__ bhh) {
    __shared__ float As[64][68];
    __shared__ float Bs[64][68];
    int m0 = blockIdx.x * 64, n0 = blockIdx.y * 64;
    int tid = threadIdx.x;
    int tx = tid & 15, ty = tid >> 4;
    float acc[4][4] = {};
    for (int kt = 0; kt < 128; kt += 64) {
        for (int i = tid; i < 64 * 16; i += 256) {
            int r = i >> 4, c = (i & 15) * 4;
            float4 v = *(const float4*)(g_fc1 + (size_t)(m0 + r) * 128 + kt + c);
            As[c + 0][r] = v.x; As[c + 1][r] = v.y; As[c + 2][r] = v.z; As[c + 3][r] = v.w;
        }
        for (int i = tid; i < 64 * 16; i += 256) {
            int r = i >> 4, c = (i & 15) * 4;
            float4 v = *(const float4*)(Wih + (size_t)(n0 + r) * 128 + kt + c);
            Bs[c + 0][r] = v.x; Bs[c + 1][r] = v.y; Bs[c + 2][r] = v.z; Bs[c + 3][r] = v.w;
        }
        __syncthreads();
#pragma unroll
        for (int k = 0; k < 64; k++) {
            float4 a4 = *(const float4*)&As[k][ty * 4];
            float4 b4 = *(const float4*)&Bs[k][tx * 4];
            float a[4] = {a4.x, a4.y, a4.z, a4.w};
            float b[4] = {b4.x, b4.y, b4.z, b4.w};
#pragma unroll
            for (int x = 0; x < 4; x++)
#pragma unroll
                for (int y = 0; y < 4; y++) acc[x][y] = fmaf(a[x], b[y], acc[x][y]);
        }
        __syncthreads();
    }
#pragma unroll
    for (int x = 0; x < 4; x++) {
        int m = m0 + ty * 4 + x;
#pragma unroll
        for (int y = 0; y < 4; y++) {
            int n = n0 + tx * 4 + y;
            g_xg0[(size_t)m * 512 + n] = acc[x][y] + bih[n] + bhh[n];
        }
    }
}

// ---------------- clustered recurrence stage ----------------
// Each of CSIZE CTAs owns EL=32 h-elements (=128 gate rows). 4 threads per row
// split K into 32-MAC quarters; butterfly-shuffle reduce; warp 0 does the
// activation and broadcasts its h slice to all cluster CTAs via DSMEM.
__device__ __forceinline__ void rec_stage(
    int rank, const float* __restrict__ xg_src, const unsigned* __restrict__ wb,
    float* __restrict__ h_stream, float* __restrict__ y_out,
    const int* wflags, int* sflag,
    float (*xgs)[128], float (*hsm)[128], float* gsm, unsigned long long* mbar)
{
    int tid = threadIdx.x;
    int p = tid >> 2, kq = tid & 3;           // row 0..127, k-quarter
    int gate = p >> 5, e = p & 31;
    int G = gate * 128 + rank * EL + e;       // global gate row

    unsigned w[16];
    {
        const unsigned* src = wb + (size_t)G * 64 + kq * 16;
#pragma unroll
        for (int i = 0; i < 16; i++) w[i] = src[i];
    }

    uint32_t hsm_l = s2u(&hsm[0][0]);
    uint32_t mb_l  = s2u(mbar);
    uint32_t hsm_r[CSIZE], mb_r[CSIZE];
#pragma unroll
    for (int q = 0; q < CSIZE; q++) {
        hsm_r[q] = mapa_u32(hsm_l, q);
        mb_r[q]  = mapa_u32(mb_l, q);
    }

    if (tid == 0) mbar_init(mb_l, CSIZE * EL);
    if (tid < 256) ((float*)hsm)[tid] = 0.f;
    __syncthreads();
    cluster_sync();

    float c = 0.f;
    for (int ck = 0; ck < NCHUNK; ck++) {
        if (wflags) {
            if (tid < CSIZE) { while (ld_acq(wflags + tid) < ck + 1) {} }
            __syncthreads();
        }
        {   // stage this CTA's 128 gate rows x 16 steps
            int s = tid >> 5, g2 = (tid >> 3) & 3, f4 = tid & 7;
            float4 v = *(const float4*)(xg_src +
                (size_t)(ck * CH + s) * 512 + g2 * 128 + rank * EL + f4 * 4);
            *(float4*)&xgs[s][g2 * EL + f4 * 4] = v;
        }
        __syncthreads();

#pragma unroll 1
        for (int s = 0; s < CH; s++) {
            int t = ck * CH + s;
            unsigned par = (unsigned)(t & 1);
            const float4* h4 = ((const float4*)&hsm[par][0]) + kq * 8;
            float a0 = 0.f, a1 = 0.f, a2 = 0.f, a3 = 0.f;
#pragma unroll
            for (int q = 0; q < 8; q++) {
                float4 hv = h4[q];
                unsigned w01 = w[2 * q], w23 = w[2 * q + 1];
                a0 = fmaf(__uint_as_float(w01 << 16), hv.x, a0);
                a1 = fmaf(__uint_as_float(w01),       hv.y, a1);
                a2 = fmaf(__uint_as_float(w23 << 16), hv.z, a2);
                a3 = fmaf(__uint_as_float(w23),       hv.w, a3);
            }
            float v = (a0 + a1) + (a2 + a3);
            v += __shfl_xor_sync(0xffffffffu, v, 1);
            v += __shfl_xor_sync(0xffffffffu, v, 2);
            if (kq == 0) gsm[p] = v + xgs[s][p];
            __syncthreads();

            if (tid < EL) {   // warp 0: activation for owned elements
                float gi = sigf(gsm[tid]);
                float gf = sigf(gsm[tid + 32]);
                float gg = tanh_(gsm[tid + 64]);
                float go = sigf(gsm[tid + 96]);
                c = fmaf(gf, c, gi * gg);
                float h = go * tanh_(c);
                int ge = rank * EL + tid;
                uint32_t off = ((par ^ 1u) * 128u + (unsigned)ge) * 4u;
#pragma unroll
                for (int q = 0; q < CSIZE; q++) st_cluster_f32(hsm_r[q] + off, h);
                if (h_stream) h_stream[(size_t)t * 128 + ge] = h;
                if (y_out && t >= S_TOT - 256)
                    y_out[(size_t)(t - (S_TOT - 256)) * 128 + ge] = h;
#pragma unroll
                for (int q = 0; q < CSIZE; q++) mbar_arrive_rel_cluster(mb_r[q]);
            }
            mbar_wait(mb_l, par);
        }
        if (sflag) {
            __syncthreads();
            if (tid == 0) {
                asm volatile("fence.acq_rel.gpu;" ::: "memory");
                st_rel(sflag, ck + 1);
            }
        }
    }
}

// ---------------- xg1 producer (cluster rank handles 4 steps/chunk) ----------------
__device__ __forceinline__ void xg1_stage(
    int rank, int seq, const int* wflags, int* sflag, float (*h0s)[128])
{
    int tid = threadIdx.x;
    const unsigned* wbp = g_wpack + 512u * 64u + (size_t)tid * 64;
    unsigned w[64];
#pragma unroll
    for (int i = 0; i < 64; i++) w[i] = wbp[i];
    float b = g_b1[tid];
    const float* h0 = g_h0 + (size_t)seq * S_TOT * 128;
    float* xg1 = g_xg1 + (size_t)seq * S_TOT * 512;
    int s0 = rank * 4;
    cluster_sync();
    for (int ck = 0; ck < NCHUNK; ck++) {
        if (tid < CSIZE) { while (ld_acq(wflags + tid) < ck + 1) {} }
        __syncthreads();
        if (tid < 128) {
            int ss = tid >> 5, f4 = tid & 31;
            *(float4*)&h0s[ss][f4 * 4] =
                *(const float4*)(h0 + (size_t)(ck * CH + s0 + ss) * 128 + f4 * 4);
        }
        __syncthreads();
#pragma unroll
        for (int ss = 0; ss < 4; ss++) {
            float v = dot128(&h0s[ss][0], w) + b;
            xg1[(size_t)(ck * CH + s0 + ss) * 512 + tid] = v;
        }
        __syncthreads();
        if (tid == 0) {
            asm volatile("fence.acq_rel.gpu;" ::: "memory");
            st_rel(sflag, ck + 1);
        }
    }
}

// ---------------- pipeline kernel: 6 clusters x 4 CTAs ----------------
__global__ void __launch_bounds__(512, 1) __cluster_dims__(CSIZE, 1, 1)
pipeline_kernel() {
    __shared__ float xgs[CH][128];
    __shared__ float hsm[2][128];
    __shared__ float gsm[128];
    __shared__ float h0s[4][128];
    __shared__ __align__(8) unsigned long long mbar;

    int cid = blockIdx.x / CSIZE;
    uint32_t rank;
    asm("mov.u32 %0, %%cluster_ctarank;" : "=r"(rank));
    int seq = cid / 3, role = cid % 3;

    if (role == 0) {
        rec_stage((int)rank, g_xg0 + (size_t)seq * S_TOT * 512, g_wpack,
                  g_h0 + (size_t)seq * S_TOT * 128, nullptr,
                  nullptr, &g_prog[seq * 8 + rank],
                  xgs, hsm, gsm, &mbar);
    } else if (role == 1) {
        xg1_stage((int)rank, seq, &g_prog[seq * 8], &g_prog[seq * 8 + 4 + rank], h0s);
    } else {
        rec_stage((int)rank, g_xg1 + (size_t)seq * S_TOT * 512,
                  g_wpack + 2u * 512u * 64u,
                  nullptr, g_y + (size_t)seq * 256u * 128u,
                  &g_prog[seq * 8 + 4], nullptr,
                  xgs, hsm, gsm, &mbar);
    }
    cluster_sync();
}

// ---------------- head ----------------
__global__ void __launch_bounds__(256) head_kernel(const float* __restrict__ Wh,
                                                   const float* __restrict__ bh,
                                                   float* __restrict__ out) {
    int r = threadIdx.x;
    const float* y1 = g_y + (size_t)r * 128;
    const float* y2 = g_y + 256u * 128u + (size_t)r * 128;
    float s1 = 0.f, s2 = 0.f;
#pragma unroll 8
    for (int k = 0; k < 128; k++) {
        float d = y1[k] - y2[k];
        float w = Wh[k];
        s1 = fmaf(w, fmaxf(d, 0.f), s1);
        s2 = fmaf(w, fmaxf(-d, 0.f), s2);
    }
    float b = bh[0];
    float p1 = s1 + b, p2 = s2 + b, pd = (s1 - s2) + b;
    float m = fmaxf(p1, fmaxf(p2, pd));
    float e1 = expf(p1 - m), e2 = expf(p2 - m), e3 = expf(pd - m);
    float inv = 1.f / (e1 + e2 + e3);
    out[r * 3 + 0] = e1 * inv;
    out[r * 3 + 1] = e2 * inv;
    out[r * 3 + 2] = e3 * inv;
}

// ---------------- launch ----------------
extern "C" void kernel_launch(void* const* d_in, const int* in_sizes, int n_in,
                              void* d_out, int out_size) {
    const float* inp1  = (const float*)d_in[0];
    const float* inp2  = (const float*)d_in[1];
    const float* Wfc   = (const float*)d_in[2];
    const float* bfc   = (const float*)d_in[3];
    const float* Wih   = (const float*)d_in[4];
    const float* Whh   = (const float*)d_in[5];
    const float* bih   = (const float*)d_in[6];
    const float* bhh   = (const float*)d_in[7];
    const float* Whead = (const float*)d_in[8];
    const float* bhead = (const float*)d_in[9];
    float* out = (float*)d_out;

    prep_kernel<<<3, 512>>>(Wih, Whh, bih, bhh);
    fc1_kernel<<<2048, 256>>>(inp1, inp2, Wfc, bfc);
    xg0_kernel<<<dim3(1024, 8), 256>>>(Wih, bih, bhh);
    pipeline_kernel<<<6 * CSIZE, 512>>>();
    head_kernel<<<1, 256>>>(Whead, bhead, out);
}

// round 5
// speedup vs baseline: 1.6189x; 1.6189x over previous
#include <cuda_runtime.h>
#include <cuda_bf16.h>
#include <cstdint>

#define S_TOT 32768
#define CH    16
#define NCHUNK (S_TOT / CH)

// ---------------- static device scratch ----------------
__device__ float g_fc1[65536u * 128u];
__device__ float g_xg0[2u * 32768u * 512u];
__device__ float g_xg1[2u * 32768u * 512u];
__device__ float g_h0 [2u * 32768u * 128u];
__device__ float g_y  [2u * 256u * 128u];
__device__ unsigned g_wpack[512u * 64u];   // Wih layer1, compensation-packed bf16x2
__device__ float g_b1[512];
__device__ int   g_prog[16];               // [seq*4 + {0:L0, 1:prod0, 2:prod1}]

// ---------------- helpers ----------------
__device__ __forceinline__ int ld_acq(const int* p) {
    int v;
    asm volatile("ld.acquire.gpu.b32 %0, [%1];" : "=r"(v) : "l"(p) : "memory");
    return v;
}
__device__ __forceinline__ void st_rel(int* p, int v) {
    asm volatile("st.release.gpu.b32 [%0], %1;" :: "l"(p), "r"(v) : "memory");
}
__device__ __forceinline__ unsigned bf16rn_bits(float f) {
    unsigned u = __float_as_uint(f);
    return ((u + 0x7fffu + ((u >> 16) & 1u)) >> 16) & 0xffffu;
}
__device__ __forceinline__ unsigned pack2(float we, float wo) {
    unsigned lo = bf16rn_bits(we);
    unsigned t  = __float_as_uint(wo) & 0xffff0000u;
    unsigned best = t | lo;
    float bd = fabsf(__uint_as_float(best) - wo);
    unsigned c = (t + 0x10000u) | lo;
    { float d = fabsf(__uint_as_float(c) - wo); if (d < bd) { bd = d; best = c; } }
    c = (t - 0x10000u) | lo;
    { float d = fabsf(__uint_as_float(c) - wo); if (d < bd) { bd = d; best = c; } }
    return best;
}
__device__ __forceinline__ float tanhap(float x) {
    float r;
    asm("tanh.approx.f32 %0, %1;" : "=f"(r) : "f"(x));
    return r;
}
__device__ __forceinline__ float sigap(float x) {
    return fmaf(0.5f, tanhap(0.5f * x), 0.5f);
}
__device__ __forceinline__ void fma2(uint64_t& acc, uint64_t a, uint64_t b) {
    asm("fma.rn.f32x2 %0, %1, %2, %0;" : "+l"(acc) : "l"(a), "l"(b));
}
__device__ __forceinline__ uint64_t pkf2(float lo, float hi) {
    uint64_t r;
    asm("mov.b64 %0, {%1, %2};" : "=l"(r) : "r"(__float_as_uint(lo)), "r"(__float_as_uint(hi)));
    return r;
}
__device__ __forceinline__ float sum2(uint64_t a) {
    unsigned lo, hi;
    asm("mov.b64 {%0, %1}, %2;" : "=r"(lo), "=r"(hi) : "l"(a));
    return __uint_as_float(lo) + __uint_as_float(hi);
}

// 128-MAC dot (producer): h in smem (broadcast), 64 packed-bf16 regs
__device__ __forceinline__ float dot128(const float* h, const unsigned* w) {
    const float4* h4 = (const float4*)h;
    float a0 = 0.f, a1 = 0.f, a2 = 0.f, a3 = 0.f;
#pragma unroll
    for (int q = 0; q < 32; q++) {
        float4 hv = h4[q];
        unsigned w01 = w[2 * q], w23 = w[2 * q + 1];
        a0 = fmaf(__uint_as_float(w01 << 16), hv.x, a0);
        a1 = fmaf(__uint_as_float(w01),       hv.y, a1);
        a2 = fmaf(__uint_as_float(w23 << 16), hv.z, a2);
        a3 = fmaf(__uint_as_float(w23),       hv.w, a3);
    }
    return (a0 + a1) + (a2 + a3);
}

// ---------------- prep: pack Wih1, bias, reset flags ----------------
__global__ void __launch_bounds__(512) prep_kernel(const float* __restrict__ Wih,
                                                   const float* __restrict__ bih,
                                                   const float* __restrict__ bhh) {
    int j = threadIdx.x;
    const float* row = Wih + 512u * 128u + (size_t)j * 128;
    unsigned* dst = g_wpack + (size_t)j * 64;
    for (int p = 0; p < 64; p++) dst[p] = pack2(row[2 * p], row[2 * p + 1]);
    g_b1[j] = bih[512 + j] + bhh[512 + j];
    if (j < 16) g_prog[j] = 0;
}

// ---------------- fc1 = relu(x @ Wfc^T + b) ----------------
__global__ void __launch_bounds__(256) fc1_kernel(const float* __restrict__ inp1,
                                                  const float* __restrict__ inp2,
                                                  const float* __restrict__ Wfc,
                                                  const float* __restrict__ bfc) {
    __shared__ float Ws[128][65];
    __shared__ float As[32][64];
    int tid = threadIdx.x;
    for (int i = tid; i < 128 * 64; i += 256) Ws[i >> 6][i & 63] = Wfc[i];
    int r0 = blockIdx.x * 32;
    for (int i = tid; i < 32 * 64; i += 256) {
        int r = r0 + (i >> 6), k = i & 63;
        const float* src = (r < S_TOT) ? (inp1 + (size_t)r * 64)
                                       : (inp2 + (size_t)(r - S_TOT) * 64);
        As[i >> 6][k] = src[k];
    }
    __syncthreads();
    int n = tid & 127, rb = (tid >> 7) * 16;
    float b = bfc[n];
    for (int rr = 0; rr < 16; rr++) {
        float acc = b;
#pragma unroll
        for (int k = 0; k < 64; k++) acc = fmaf(As[rb + rr][k], Ws[n][k], acc);
        g_fc1[(size_t)(r0 + rb + rr) * 128 + n] = fmaxf(acc, 0.f);
    }
}

// ---------------- xg0 = fc1 @ Wih0^T + (bih0+bhh0) ----------------
__global__ void __launch_bounds__(256) xg0_kernel(const float* __restrict__ Wih,
                                                  const float* __restrict__ bih,
                                                  const float* __restrict__ bhh) {
    __shared__ float As[64][68];
    __shared__ float Bs[64][68];
    int m0 = blockIdx.x * 64, n0 = blockIdx.y * 64;
    int tid = threadIdx.x;
    int tx = tid & 15, ty = tid >> 4;
    float acc[4][4] = {};
    for (int kt = 0; kt < 128; kt += 64) {
        for (int i = tid; i < 64 * 16; i += 256) {
            int r = i >> 4, c = (i & 15) * 4;
            float4 v = *(const float4*)(g_fc1 + (size_t)(m0 + r) * 128 + kt + c);
            As[c + 0][r] = v.x; As[c + 1][r] = v.y; As[c + 2][r] = v.z; As[c + 3][r] = v.w;
        }
        for (int i = tid; i < 64 * 16; i += 256) {
            int r = i >> 4, c = (i & 15) * 4;
            float4 v = *(const float4*)(Wih + (size_t)(n0 + r) * 128 + kt + c);
            Bs[c + 0][r] = v.x; Bs[c + 1][r] = v.y; Bs[c + 2][r] = v.z; Bs[c + 3][r] = v.w;
        }
        __syncthreads();
#pragma unroll
        for (int k = 0; k < 64; k++) {
            float4 a4 = *(const float4*)&As[k][ty * 4];
            float4 b4 = *(const float4*)&Bs[k][tx * 4];
            float a[4] = {a4.x, a4.y, a4.z, a4.w};
            float bb[4] = {b4.x, b4.y, b4.z, b4.w};
#pragma unroll
            for (int x = 0; x < 4; x++)
#pragma unroll
                for (int y = 0; y < 4; y++) acc[x][y] = fmaf(a[x], bb[y], acc[x][y]);
        }
        __syncthreads();
    }
#pragma unroll
    for (int x = 0; x < 4; x++) {
        int m = m0 + ty * 4 + x;
#pragma unroll
        for (int y = 0; y < 4; y++) {
            int n = n0 + tx * 4 + y;
            g_xg0[(size_t)m * 512 + n] = acc[x][y] + bih[n] + bhh[n];
        }
    }
}

// ---------------- recurrence: 256 threads, f32x2 dot, warp-local gates ----------------
__device__ void rec2(const float* __restrict__ whh,     // [512][128] fp32 this layer
                     const float* __restrict__ xg_src,
                     float* __restrict__ h_stream,      // L0 only
                     float* __restrict__ y_out,         // L1 only
                     const int* wflags, int nwf, int* sflag)
{
    __shared__ float xgs[CH * 512];
    __shared__ float hsm[2][128];
    int tid = threadIdx.x;
    int wz = tid >> 5, l = tid & 31;
    int half = l >> 4, e = wz * 16 + (l & 15);   // element 0..127
    int rA = half * 256 + e, rB = rA + 128;      // half0: i,f rows; half1: g,o rows

    // full-precision fp32 weight pairs, register-resident (64 b64 per row)
    uint64_t wA[64], wB[64];
    {
        const uint64_t* pa = (const uint64_t*)(whh + (size_t)rA * 128);
        const uint64_t* pb = (const uint64_t*)(whh + (size_t)rB * 128);
#pragma unroll
        for (int i = 0; i < 64; i++) { wA[i] = pa[i]; wB[i] = pb[i]; }
    }
    hsm[tid >> 7][tid & 127] = 0.f;
    float c = 0.f;
    __syncthreads();

    for (int t = 0; t < S_TOT; t++) {
        int s = t & (CH - 1);
        if (s == 0) {
            int ck = t >> 4;
            if (nwf) {
                if (tid < nwf) { while (ld_acq(wflags + tid) < ck + 1) {} }
                __syncthreads();
            }
            const float4* src = (const float4*)(xg_src + (size_t)ck * CH * 512);
            float4* dst = (float4*)xgs;
#pragma unroll
            for (int q = 0; q < 8; q++) dst[tid + 256 * q] = src[tid + 256 * q];
            __syncthreads();
        }
        int par = t & 1;
        const float4* h4 = (const float4*)&hsm[par][0];
        uint64_t aA0 = 0ull, aA1 = 0ull, aB0 = 0ull, aB1 = 0ull;
#pragma unroll
        for (int q = 0; q < 32; q++) {
            float4 hv = h4[q];
            uint64_t h01 = pkf2(hv.x, hv.y);
            uint64_t h23 = pkf2(hv.z, hv.w);
            fma2(aA0, wA[2 * q],     h01);
            fma2(aA1, wA[2 * q + 1], h23);
            fma2(aB0, wB[2 * q],     h01);
            fma2(aB1, wB[2 * q + 1], h23);
        }
        float vA = (sum2(aA0) + sum2(aA1)) + xgs[s * 512 + rA];
        float vB = (sum2(aB0) + sum2(aB1)) + xgs[s * 512 + rB];

        float actA, actB;
        if (half == 0) { actA = sigap(vA);  actB = sigap(vB); }   // i, f
        else           { actA = tanhap(vA); actB = sigap(vB); }   // g, o
        float pA = __shfl_xor_sync(0xffffffffu, actA, 16);
        float pB = __shfl_xor_sync(0xffffffffu, actB, 16);
        if (half == 0) {
            c = fmaf(actB, c, actA * pA);        // f*c + i*g
            float h = pB * tanhap(c);            // o * tanh(c)
            hsm[par ^ 1][e] = h;
            if (h_stream) h_stream[(size_t)t * 128 + e] = h;
            if (y_out && t >= S_TOT - 256)
                y_out[(size_t)(t - (S_TOT - 256)) * 128 + e] = h;
        }
        __syncthreads();
        if (sflag && s == CH - 1 && tid == 0) {
            asm volatile("fence.acq_rel.gpu;" ::: "memory");
            st_rel(sflag, (t >> 4) + 1);
        }
    }
}

// ---------------- xg1 producer: 256 threads, 256 gate rows per CTA ----------------
__device__ void producer2(int seq, int halfCTA, const int* wflag, int* sflag)
{
    __shared__ float h0s[CH][128];
    int tid = threadIdx.x;
    int G = halfCTA * 256 + tid;
    const unsigned* ws = g_wpack + (size_t)G * 64;
    unsigned w[64];
#pragma unroll
    for (int i = 0; i < 64; i++) w[i] = ws[i];
    float b = g_b1[G];
    const float* h0 = g_h0 + (size_t)seq * S_TOT * 128;
    float* xg1 = g_xg1 + (size_t)seq * S_TOT * 512;

    for (int ck = 0; ck < NCHUNK; ck++) {
        if (tid == 0) { while (ld_acq(wflag) < ck + 1) {} }
        __syncthreads();
        {
            const float4* src = (const float4*)(h0 + (size_t)ck * CH * 128);
            float4* dst = (float4*)&h0s[0][0];
            dst[tid]       = src[tid];
            dst[tid + 256] = src[tid + 256];
        }
        __syncthreads();
#pragma unroll 1
        for (int ss = 0; ss < CH; ss++) {
            float v = dot128(&h0s[ss][0], w) + b;
            xg1[(size_t)(ck * CH + ss) * 512 + G] = v;
        }
        __syncthreads();
        if (tid == 0) {
            asm volatile("fence.acq_rel.gpu;" ::: "memory");
            st_rel(sflag, ck + 1);
        }
    }
}

// ---------------- pipeline: 8 CTAs = 2 seq x {L0rec, prod0, prod1, L1rec} ----------------
__global__ void __launch_bounds__(256, 1) pipeline2(const float* __restrict__ whh) {
    int b = blockIdx.x, seq = b >> 2, role = b & 3;
    if (role == 0) {
        rec2(whh, g_xg0 + (size_t)seq * S_TOT * 512,
             g_h0 + (size_t)seq * S_TOT * 128, nullptr,
             nullptr, 0, &g_prog[seq * 4]);
    } else if (role == 3) {
        rec2(whh + 512u * 128u, g_xg1 + (size_t)seq * S_TOT * 512,
             nullptr, g_y + (size_t)seq * 256u * 128u,
             &g_prog[seq * 4 + 1], 2, nullptr);
    } else {
        producer2(seq, role - 1, &g_prog[seq * 4], &g_prog[seq * 4 + role]);
    }
}

// ---------------- head ----------------
__global__ void __launch_bounds__(256) head_kernel(const float* __restrict__ Wh,
                                                   const float* __restrict__ bh,
                                                   float* __restrict__ out) {
    int r = threadIdx.x;
    const float* y1 = g_y + (size_t)r * 128;
    const float* y2 = g_y + 256u * 128u + (size_t)r * 128;
    float s1 = 0.f, s2 = 0.f;
#pragma unroll 8
    for (int k = 0; k < 128; k++) {
        float d = y1[k] - y2[k];
        float w = Wh[k];
        s1 = fmaf(w, fmaxf(d, 0.f), s1);
        s2 = fmaf(w, fmaxf(-d, 0.f), s2);
    }
    float b = bh[0];
    float p1 = s1 + b, p2 = s2 + b, pd = (s1 - s2) + b;
    float m = fmaxf(p1, fmaxf(p2, pd));
    float e1 = expf(p1 - m), e2 = expf(p2 - m), e3 = expf(pd - m);
    float inv = 1.f / (e1 + e2 + e3);
    out[r * 3 + 0] = e1 * inv;
    out[r * 3 + 1] = e2 * inv;
    out[r * 3 + 2] = e3 * inv;
}

// ---------------- launch ----------------
extern "C" void kernel_launch(void* const* d_in, const int* in_sizes, int n_in,
                              void* d_out, int out_size) {
    const float* inp1  = (const float*)d_in[0];
    const float* inp2  = (const float*)d_in[1];
    const float* Wfc   = (const float*)d_in[2];
    const float* bfc   = (const float*)d_in[3];
    const float* Wih   = (const float*)d_in[4];
    const float* Whh   = (const float*)d_in[5];
    const float* bih   = (const float*)d_in[6];
    const float* bhh   = (const float*)d_in[7];
    const float* Whead = (const float*)d_in[8];
    const float* bhead = (const float*)d_in[9];
    float* out = (float*)d_out;

    prep_kernel<<<1, 512>>>(Wih, bih, bhh);
    fc1_kernel<<<2048, 256>>>(inp1, inp2, Wfc, bfc);
    xg0_kernel<<<dim3(1024, 8), 256>>>(Wih, bih, bhh);
    pipeline2<<<8, 256>>>(Whh);
    head_kernel<<<1, 256>>>(Whead, bhead, out);
}